// round 1
// baseline (speedup 1.0000x reference)
#include <cuda_runtime.h>

// LIF spike neuron: per-row scan over T=100.
//   mem = mem*TAU + x_t - w
//   spike = (mem - THRESH) > 0
//   w = BETA*w + (1-BETA)*(A*mem + B*spike)   (mem before soft reset)
//   mem -= spike*THRESH
// x: [B=64, N=8192, T=100] fp32, T contiguous. out: same shape, fp32 spikes.

#define TAU    0.5f
#define THRESH 0.5f
#define BETA   0.9f
#define ONE_MB 0.1f   // 1 - BETA
#define A_C    0.5f
#define B_C    0.5f

__device__ __forceinline__ void lif_step(float xt, float& mem, float& w, float& s) {
    mem = fmaf(mem, TAU, xt) - w;
    s = (mem > THRESH) ? 1.0f : 0.0f;
    w = fmaf(BETA, w, ONE_MB * fmaf(A_C, mem, B_C * s));
    mem = fmaf(-s, THRESH, mem);
}

__global__ __launch_bounds__(256) void lif_kernel(const float4* __restrict__ x,
                                                  float4* __restrict__ out,
                                                  int rows) {
    int r = blockIdx.x * blockDim.x + threadIdx.x;
    if (r >= rows) return;

    const float4* xr = x + (size_t)r * 25;   // 100 floats = 25 float4
    float4* outr = out + (size_t)r * 25;

    float mem = 0.0f, w = 0.0f;

    #pragma unroll
    for (int j = 0; j < 25; j++) {
        float4 v = xr[j];
        float4 s;
        lif_step(v.x, mem, w, s.x);
        lif_step(v.y, mem, w, s.y);
        lif_step(v.z, mem, w, s.z);
        lif_step(v.w, mem, w, s.w);
        outr[j] = s;
    }
}

extern "C" void kernel_launch(void* const* d_in, const int* in_sizes, int n_in,
                              void* d_out, int out_size) {
    const float* x = (const float*)d_in[0];
    float* out = (float*)d_out;
    int rows = in_sizes[0] / 100;   // 64*8192 = 524288

    int block = 256;
    int grid = (rows + block - 1) / block;
    lif_kernel<<<grid, block>>>((const float4*)x, (float4*)out, rows);
}

// round 2
// speedup vs baseline: 1.5834x; 1.5834x over previous
#include <cuda_runtime.h>

// LIF spike scan, x: [64, 8192, 100] fp32 (T contiguous), out: same-shape spikes.
//   mem = mem*TAU + x_t - w
//   spike = (mem - THRESH) > 0
//   w = BETA*w + (1-BETA)*(A*mem + B*spike)
//   mem -= spike*THRESH
//
// Strategy: shared-memory staging for fully coalesced HBM traffic.
// Block of 256 threads owns 256 rows (one row per thread for the scan).
// Smem rows padded to stride 101 (gcd(101 mod 32, 32) = gcd(5,32)=1) so the
// per-thread scan phase is bank-conflict-free.

#define TAU    0.5f
#define THRESH 0.5f
#define BETA   0.9f
#define ONE_MB 0.1f   // 1 - BETA
#define A_C    0.5f
#define B_C    0.5f

constexpr int T_LEN  = 100;
constexpr int STRIDE = 101;       // padded smem row stride (floats)
constexpr int ROWS   = 256;       // rows per block == threads per block
constexpr int SMEM_BYTES = ROWS * STRIDE * 4;   // 103,424 B

__global__ __launch_bounds__(ROWS, 2) void lif_kernel(const float* __restrict__ x,
                                                      float* __restrict__ out) {
    extern __shared__ float s[];
    const int tid = threadIdx.x;
    const size_t base = (size_t)blockIdx.x * ROWS * T_LEN;
    const float* __restrict__ xin  = x   + base;
    float* __restrict__       xout = out + base;

    // ---- Stage in: fully coalesced (consecutive 4B per lane) ----
    #pragma unroll 5
    for (int i = 0; i < T_LEN; i++) {
        int g   = i * ROWS + tid;          // 0 .. 25599
        int row = g / T_LEN;               // mul-shift
        int t   = g - row * T_LEN;
        s[row * STRIDE + t] = xin[g];
    }
    __syncthreads();

    // ---- Scan: one thread per row, conflict-free smem, in-place spikes ----
    {
        float mem = 0.0f, w = 0.0f;
        float* srow = s + tid * STRIDE;
        #pragma unroll 10
        for (int t = 0; t < T_LEN; t++) {
            float xt = srow[t];
            mem = fmaf(mem, TAU, xt) - w;
            float sp = (mem > THRESH) ? 1.0f : 0.0f;
            w = fmaf(BETA, w, ONE_MB * fmaf(A_C, mem, B_C * sp));
            mem = fmaf(-sp, THRESH, mem);
            srow[t] = sp;
        }
    }
    __syncthreads();

    // ---- Stage out: fully coalesced ----
    #pragma unroll 5
    for (int i = 0; i < T_LEN; i++) {
        int g   = i * ROWS + tid;
        int row = g / T_LEN;
        int t   = g - row * T_LEN;
        xout[g] = s[row * STRIDE + t];
    }
}

extern "C" void kernel_launch(void* const* d_in, const int* in_sizes, int n_in,
                              void* d_out, int out_size) {
    const float* x = (const float*)d_in[0];
    float* out = (float*)d_out;
    int rows = in_sizes[0] / T_LEN;            // 524288
    int grid = rows / ROWS;                    // 2048 (divides exactly)

    cudaFuncSetAttribute(lif_kernel, cudaFuncAttributeMaxDynamicSharedMemorySize,
                         SMEM_BYTES);
    lif_kernel<<<grid, ROWS, SMEM_BYTES>>>(x, out);
}

// round 3
// speedup vs baseline: 3.2521x; 2.0538x over previous
#include <cuda_runtime.h>
#include <cstdint>

// LIF spike scan. x: [64, 8192, 100] fp32 (T contiguous), out: spikes, same shape.
//   mem = mem*TAU + x_t - w ; spike = (mem > THRESH)
//   w = BETA*w + (1-BETA)*(A*mem + B*spike) ; mem -= spike*THRESH
//
// R3: TMA bulk staging (smem stride == 100 makes the smem image exactly linear
// in global order => pure bulk copy), conflict-free float4 smem scan
// (100 % 32 == 4 => quarter-warp LDS.128 covers all 32 banks), 51.2KB smem
// => 4 CTAs/SM for phase overlap.

#define TAU    0.5f
#define THRESH 0.5f
#define BETA   0.9f
#define A_C    0.5f
#define B_C    0.5f
// w = BETA*w + 0.1*(0.5*mem + 0.5*s) = BETA*w + 0.05*mem + 0.05*s
#define C_MS   0.05f

constexpr int T_LEN      = 100;
constexpr int ROWS       = 128;                  // rows per CTA == threads
constexpr int TILE_FLOATS = ROWS * T_LEN;        // 12800
constexpr int TILE_BYTES  = TILE_FLOATS * 4;     // 51200
constexpr int SMEM_BYTES  = 16 + TILE_BYTES;     // mbarrier (16B slot) + data

__device__ __forceinline__ void lif_step(float xt, float& mem, float& w, float& sp) {
    mem = fmaf(mem, TAU, xt) - w;
    sp = (mem > THRESH) ? 1.0f : 0.0f;
    w  = fmaf(BETA, w, fmaf(C_MS, mem, C_MS * sp));
    mem = fmaf(-sp, THRESH, mem);
}

__global__ __launch_bounds__(ROWS, 4) void lif_kernel(const float* __restrict__ x,
                                                      float* __restrict__ out) {
    extern __shared__ float smem[];
    const int tid = threadIdx.x;

    uint32_t smem_u32;
    asm("{ .reg .u64 t; cvta.to.shared.u64 t, %1; cvt.u32.u64 %0, t; }"
        : "=r"(smem_u32) : "l"(smem));
    const uint32_t mbar_addr = smem_u32;        // [0,8): mbarrier
    const uint32_t data_addr = smem_u32 + 16;   // 16B-aligned tile
    float* s = smem + 4;

    const float* __restrict__ xin  = x   + (size_t)blockIdx.x * TILE_FLOATS;
    float* __restrict__       xout = out + (size_t)blockIdx.x * TILE_FLOATS;

    // ---- mbarrier init + bulk load (TMA) ----
    if (tid == 0) {
        asm volatile("mbarrier.init.shared.b64 [%0], 1;" :: "r"(mbar_addr) : "memory");
    }
    __syncthreads();
    if (tid == 0) {
        asm volatile("mbarrier.arrive.expect_tx.shared.b64 _, [%0], %1;"
                     :: "r"(mbar_addr), "r"((uint32_t)TILE_BYTES) : "memory");
        asm volatile("cp.async.bulk.shared::cta.global.mbarrier::complete_tx::bytes "
                     "[%0], [%1], %2, [%3];"
                     :: "r"(data_addr), "l"(xin), "r"((uint32_t)TILE_BYTES),
                        "r"(mbar_addr) : "memory");
    }
    // wait (parity 0), acquire for the LDS reads that follow
    {
        uint32_t done;
        asm volatile(
            "{\n\t.reg .pred p;\n\t"
            "mbarrier.try_wait.parity.acquire.cta.shared::cta.b64 p, [%1], 0;\n\t"
            "selp.b32 %0, 1, 0, p;\n\t}"
            : "=r"(done) : "r"(mbar_addr) : "memory");
        if (!done) {
            asm volatile(
                "{\n\t.reg .pred P1;\n\t"
                "WL_%=:\n\t"
                "mbarrier.try_wait.parity.acquire.cta.shared::cta.b64 P1, [%0], 0, 0x989680;\n\t"
                "@P1 bra.uni WD_%=;\n\t"
                "bra.uni WL_%=;\n\t"
                "WD_%=:\n\t}"
                :: "r"(mbar_addr) : "memory");
        }
    }

    // ---- scan: one thread per row; float4 smem access is bank-conflict-free ----
    {
        float4* srow = reinterpret_cast<float4*>(s + tid * T_LEN);
        float mem = 0.0f, w = 0.0f;
        #pragma unroll
        for (int j = 0; j < T_LEN / 4; j++) {
            float4 v = srow[j];
            float4 sp;
            lif_step(v.x, mem, w, sp.x);
            lif_step(v.y, mem, w, sp.y);
            lif_step(v.z, mem, w, sp.z);
            lif_step(v.w, mem, w, sp.w);
            srow[j] = sp;
        }
    }
    __syncthreads();
    asm volatile("fence.proxy.async.shared::cta;" ::: "memory");

    // ---- bulk store (TMA) smem -> gmem ----
    if (tid == 0) {
        asm volatile("cp.async.bulk.global.shared::cta.bulk_group [%0], [%1], %2;"
                     :: "l"(xout), "r"(data_addr), "r"((uint32_t)TILE_BYTES) : "memory");
        asm volatile("cp.async.bulk.commit_group;" ::: "memory");
        asm volatile("cp.async.bulk.wait_group 0;" ::: "memory");
    }
}

extern "C" void kernel_launch(void* const* d_in, const int* in_sizes, int n_in,
                              void* d_out, int out_size) {
    const float* x = (const float*)d_in[0];
    float* out = (float*)d_out;
    int rows = in_sizes[0] / T_LEN;       // 524288
    int grid = rows / ROWS;               // 4096

    cudaFuncSetAttribute(lif_kernel, cudaFuncAttributeMaxDynamicSharedMemorySize,
                         SMEM_BYTES);
    lif_kernel<<<grid, ROWS, SMEM_BYTES>>>(x, out);
}